// round 13
// baseline (speedup 1.0000x reference)
#include <cuda_runtime.h>
#include <cuda_fp16.h>
#include <cstdint>

// ---------------- problem constants ----------------
#define Bq      32
#define Sq      4096
#define Dq      64
#define Pq      8
#define STRIDEq 4
#define Hq      512
#define Tq      1023
#define Mrows   (Bq * Tq)     // 32736
#define Mpad    32768
#define Kdim    512

// ---------------- device-global scratch (allocation-free rule) ----------
__device__ __align__(256) __half g_Ah[(size_t)Mpad * Kdim];  // fp16(A)
__device__ __align__(256) __half g_Wh[Kdim * Hq];            // fp16(W)

// ---------------- PTX helpers ----------------
__device__ __forceinline__ uint32_t smem_u32(const void* p) {
    uint32_t a;
    asm("{ .reg .u64 t; cvta.to.shared.u64 t, %1; cvt.u32.u64 %0, t; }" : "=r"(a) : "l"(p));
    return a;
}

#define CP_ASYNC16(dst, src) \
    asm volatile("cp.async.cg.shared.global [%0], [%1], 16;" \
                 :: "r"((uint32_t)(dst)), "l"(__cvta_generic_to_global(src)) : "memory")
#define CP_COMMIT()  asm volatile("cp.async.commit_group;" ::: "memory")
#define CP_WAIT6()   asm volatile("cp.async.wait_group 6;" ::: "memory")

#define LDSM4(r, addr) \
    asm volatile("ldmatrix.sync.aligned.m8n8.x4.shared.b16 {%0,%1,%2,%3}, [%4];" \
                 : "=r"((r)[0]), "=r"((r)[1]), "=r"((r)[2]), "=r"((r)[3]) : "r"(addr))
#define LDSM4T(r, addr) \
    asm volatile("ldmatrix.sync.aligned.m8n8.x4.trans.shared.b16 {%0,%1,%2,%3}, [%4];" \
                 : "=r"((r)[0]), "=r"((r)[1]), "=r"((r)[2]), "=r"((r)[3]) : "r"(addr))

#define MMA16816(d, a, b0_, b1_) \
    asm volatile("mma.sync.aligned.m16n8k16.row.col.f32.f16.f16.f32 " \
                 "{%0,%1,%2,%3}, {%4,%5,%6,%7}, {%8,%9}, {%0,%1,%2,%3};" \
                 : "+f"((d)[0]), "+f"((d)[1]), "+f"((d)[2]), "+f"((d)[3]) \
                 : "r"((a)[0]), "r"((a)[1]), "r"((a)[2]), "r"((a)[3]), \
                   "r"(b0_), "r"(b1_))

__device__ __forceinline__ uint32_t pack_h2(__half a, __half b) {
    __half2 t = __halves2half2(a, b);
    return *reinterpret_cast<uint32_t*>(&t);
}

// -------------------------------------------------------------------------
// Kernel 1: gather tokens + fp16(A), PLUS W->fp16 convert in extra blocks.
// blocks [0, 8192): gather 4 rows each; blocks [8192, 8704): wconv.
// -------------------------------------------------------------------------
#define GATHER_BLKS (Mpad / 4)     // 8192
#define WCONV_BLKS  512

__global__ void gather_wconv_kernel(const float* __restrict__ x,
                                    const int*   __restrict__ lengths,
                                    const float* __restrict__ W,
                                    float* __restrict__ tok,
                                    float* __restrict__ out_len)
{
    const int i = threadIdx.x;

    if (blockIdx.x >= GATHER_BLKS) {      // ---- wconv part ----
        const int wi = (blockIdx.x - GATHER_BLKS) * 128 + i;   // float4 idx
        const float4 v = reinterpret_cast<const float4*>(W)[wi];
        uint2 uh;
        uh.x = pack_h2(__float2half(v.x), __float2half(v.y));
        uh.y = pack_h2(__float2half(v.z), __float2half(v.w));
        reinterpret_cast<uint2*>(g_Wh)[wi] = uh;
        return;
    }

    #pragma unroll
    for (int rr = 0; rr < 4; rr++) {
        const int row = blockIdx.x * 4 + rr;
        float4 v = make_float4(0.f, 0.f, 0.f, 0.f);
        if (row < Mrows) {
            const int b = row / Tq;
            const int t = row - b * Tq;
            const int ntok = (lengths[b] - Pq) / STRIDEq + 1;
            if (t < ntok) {
                const int p  = i >> 4;
                const int d4 = i & 15;
                v = reinterpret_cast<const float4*>(
                        x + ((size_t)b * Sq + (size_t)t * STRIDEq + p) * Dq)[d4];
            }
            reinterpret_cast<float4*>(tok + (size_t)row * Kdim)[i] = v;
        }
        uint2 uh;
        uh.x = pack_h2(__float2half(v.x), __float2half(v.y));
        uh.y = pack_h2(__float2half(v.z), __float2half(v.w));
        reinterpret_cast<uint2*>(g_Ah)[(size_t)row * 128 + i] = uh;
    }
    if (blockIdx.x == 0 && i < Bq)
        out_len[i] = (float)((lengths[i] - Pq) / STRIDEq + 1);
}

// -------------------------------------------------------------------------
// Kernel 2: plain fp16 GEMM, mma.sync.m16n8k16, 8-stage cp.async ring.
// CTA 128x128, BK=32, 256 threads = 8 warps (warp 64x32), occ 1.
// 7 stages prefetched ahead; uniform wait_group 6 via empty-commit trick.
// Waves: 1024 CTAs / 148 SMs = 6.92 -> tail ~1.2% (vs 15.6% at occ 2).
// -------------------------------------------------------------------------
#define BKq       32
#define A_STRIDE  80
#define W_STRIDE  272
#define A_BUF     (128 * A_STRIDE)          // 10240
#define W_BUF     (BKq * W_STRIDE)          // 8704
#define STAGE_B   (A_BUF + W_BUF)           // 18944
#define NSTAGE    8
#define GEMM_SMEM (NSTAGE * STAGE_B)        // 151552 -> forces occ 1

__global__ __launch_bounds__(256, 1)
void gemm_mma_kernel(const float* __restrict__ bias,
                     float* __restrict__ hidden)
{
    extern __shared__ char sm[];
    const uint32_t sbase = smem_u32(sm);

    const int tid  = threadIdx.x;
    const int n0   = blockIdx.x * 128;
    const int m0   = blockIdx.y * 128;
    const int w    = tid >> 5;
    const int lane = tid & 31;
    const int wm   = (w >> 2) * 64;      // 0 / 64
    const int wn   = (w & 3) * 32;       // 0/32/64/96

    float acc[4][4][4];
    #pragma unroll
    for (int a = 0; a < 4; a++)
        #pragma unroll
        for (int b = 0; b < 4; b++)
            #pragma unroll
            for (int c = 0; c < 4; c++) acc[a][b][c] = 0.f;

    auto load_stage = [&](int buf, int k0) {
        const uint32_t st = sbase + buf * STAGE_B;
        #pragma unroll
        for (int j = 0; j < 2; j++) {                 // A: 512 16B chunks
            const int i = j * 256 + tid;
            const int row = i >> 2, c = i & 3;
            CP_ASYNC16(st + row * A_STRIDE + c * 16,
                       g_Ah + (size_t)(m0 + row) * Kdim + k0 + c * 8);
        }
        #pragma unroll
        for (int j = 0; j < 2; j++) {                 // W: 512 16B chunks
            const int i = j * 256 + tid;
            const int kr = i >> 4, ch = i & 15;
            CP_ASYNC16(st + A_BUF + kr * W_STRIDE + ch * 16,
                       g_Wh + (size_t)(k0 + kr) * Hq + n0 + ch * 8);
        }
        CP_COMMIT();
    };

    // prologue: 7 stages in flight
    #pragma unroll
    for (int st = 0; st < 7; st++) load_stage(st, st * BKq);

    #pragma unroll 1
    for (int s = 0; s < 16; s++) {
        // committed groups so far = 7 + s; wait_group 6 => stage s complete
        CP_WAIT6();
        __syncthreads();          // readers of buf (s+7)&7 (= stage s-1) done
        if (s + 7 < 16) load_stage((s + 7) & 7, (s + 7) * BKq);
        else            CP_COMMIT();                   // empty group keeps count

        const uint32_t st   = sbase + (s & 7) * STAGE_B;
        const uint32_t Ah_b = st;
        const uint32_t Wh_b = st + A_BUF;

        #pragma unroll
        for (int kk = 0; kk < 2; kk++) {
            const int k16 = kk * 16;
            uint32_t aX[4][4], bH[2][4];

            const int arow  = lane & 15;
            const int acolB = (k16 + ((lane >> 4) << 3)) * 2;
            const int brow  = k16 + (lane & 15);
            const int bhalf = (lane >> 4) << 3;

            #pragma unroll
            for (int im = 0; im < 4; im++)
                LDSM4(aX[im], Ah_b + (wm + im * 16 + arow) * A_STRIDE + acolB);
            #pragma unroll
            for (int in = 0; in < 2; in++)
                LDSM4T(bH[in], Wh_b + brow * W_STRIDE + (wn + in * 16 + bhalf) * 2);

            #pragma unroll
            for (int im = 0; im < 4; im++)
                #pragma unroll
                for (int in = 0; in < 2; in++) {
                    MMA16816(acc[im][2 * in],     aX[im], bH[in][0], bH[in][1]);
                    MMA16816(acc[im][2 * in + 1], aX[im], bH[in][2], bH[in][3]);
                }
        }
    }

    // ---- epilogue: + bias, guarded stores ----
    #pragma unroll
    for (int im = 0; im < 4; im++) {
        const int gm = m0 + wm + im * 16 + (lane >> 2);
        #pragma unroll
        for (int j = 0; j < 4; j++) {
            const int gn = n0 + wn + j * 8 + 2 * (lane & 3);
            const float b0 = __ldg(bias + gn), b1 = __ldg(bias + gn + 1);
            if (gm < Mrows) {
                float2 v = make_float2(acc[im][j][0] + b0, acc[im][j][1] + b1);
                *reinterpret_cast<float2*>(hidden + (size_t)gm * Hq + gn) = v;
            }
            if (gm + 8 < Mrows) {
                float2 v = make_float2(acc[im][j][2] + b0, acc[im][j][3] + b1);
                *reinterpret_cast<float2*>(hidden + (size_t)(gm + 8) * Hq + gn) = v;
            }
        }
    }
}

// -------------------------------------------------------------------------
// Kernel 3: in-place RMSNorm. 256-thread blocks, 2 rows per block
// (measured-best config).
// -------------------------------------------------------------------------
__global__ __launch_bounds__(256)
void rmsnorm_kernel(float* __restrict__ h,
                    const float* __restrict__ scale)
{
    const int rloc = threadIdx.x >> 7;
    const int row  = blockIdx.x * 2 + rloc;
    const int i    = threadIdx.x & 127;
    const int wrp  = threadIdx.x >> 5;

    float4* hp = reinterpret_cast<float4*>(h + (size_t)row * Hq);
    float4 v = hp[i];
    float ss = v.x * v.x + v.y * v.y + v.z * v.z + v.w * v.w;
    #pragma unroll
    for (int o = 16; o > 0; o >>= 1)
        ss += __shfl_down_sync(0xffffffffu, ss, o);

    __shared__ float red[8];
    if ((threadIdx.x & 31) == 0) red[wrp] = ss;
    __syncthreads();
    const int rb = rloc * 4;
    const float tot = red[rb] + red[rb + 1] + red[rb + 2] + red[rb + 3];
    const float inv = rsqrtf(tot * (1.0f / 512.0f) + 1e-6f);

    const float4 s = reinterpret_cast<const float4*>(scale)[i];
    v.x *= inv * s.x;  v.y *= inv * s.y;
    v.z *= inv * s.z;  v.w *= inv * s.w;
    hp[i] = v;
}

// -------------------------------------------------------------------------
// launch. output: [hidden M*512][token_lengths 32][tokens M*512]
// -------------------------------------------------------------------------
extern "C" void kernel_launch(void* const* d_in, const int* in_sizes, int n_in,
                              void* d_out, int out_size)
{
    const float* x       = (const float*)d_in[0];
    const int*   lengths = (const int*)  d_in[1];
    const float* W       = (const float*)d_in[2];
    const float* bias    = (const float*)d_in[3];
    const float* scale   = (const float*)d_in[4];

    float* out        = (float*)d_out;
    float* out_hidden = out;
    float* out_len    = out + (size_t)Mrows * Hq;
    float* out_tokens = out + (size_t)Mrows * Hq + Bq;

    cudaFuncSetAttribute(gemm_mma_kernel,
                         cudaFuncAttributeMaxDynamicSharedMemorySize, GEMM_SMEM);

    gather_wconv_kernel<<<GATHER_BLKS + WCONV_BLKS, 128>>>(
        x, lengths, W, out_tokens, out_len);
    gemm_mma_kernel<<<dim3(4, 256), 256, GEMM_SMEM>>>(bias, out_hidden);
    rmsnorm_kernel<<<Mrows / 2, 256>>>(out_hidden, scale);
}

// round 14
// speedup vs baseline: 1.2346x; 1.2346x over previous
#include <cuda_runtime.h>
#include <cuda_fp16.h>
#include <cstdint>

// ---------------- problem constants ----------------
#define Bq      32
#define Sq      4096
#define Dq      64
#define Pq      8
#define STRIDEq 4
#define Hq      512
#define Tq      1023
#define Mrows   (Bq * Tq)     // 32736
#define Mpad    32768
#define Kdim    512

// ---------------- device-global scratch (allocation-free rule) ----------
__device__ __align__(256) __half g_Ah[(size_t)Mpad * Kdim];  // fp16(A)
__device__ __align__(256) __half g_Wh[Kdim * Hq];            // fp16(W)

// ---------------- PTX helpers ----------------
__device__ __forceinline__ uint32_t smem_u32(const void* p) {
    uint32_t a;
    asm("{ .reg .u64 t; cvta.to.shared.u64 t, %1; cvt.u32.u64 %0, t; }" : "=r"(a) : "l"(p));
    return a;
}

#define CP_ASYNC16(dst, src) \
    asm volatile("cp.async.cg.shared.global [%0], [%1], 16;" \
                 :: "r"((uint32_t)(dst)), "l"(__cvta_generic_to_global(src)) : "memory")
#define CP_COMMIT()  asm volatile("cp.async.commit_group;" ::: "memory")
#define CP_WAIT2()   asm volatile("cp.async.wait_group 2;" ::: "memory")
#define CP_WAIT0()   asm volatile("cp.async.wait_group 0;" ::: "memory")

#define LDSM4(r, addr) \
    asm volatile("ldmatrix.sync.aligned.m8n8.x4.shared.b16 {%0,%1,%2,%3}, [%4];" \
                 : "=r"((r)[0]), "=r"((r)[1]), "=r"((r)[2]), "=r"((r)[3]) : "r"(addr))
#define LDSM4T(r, addr) \
    asm volatile("ldmatrix.sync.aligned.m8n8.x4.trans.shared.b16 {%0,%1,%2,%3}, [%4];" \
                 : "=r"((r)[0]), "=r"((r)[1]), "=r"((r)[2]), "=r"((r)[3]) : "r"(addr))

#define MMA16816(d, a, b0_, b1_) \
    asm volatile("mma.sync.aligned.m16n8k16.row.col.f32.f16.f16.f32 " \
                 "{%0,%1,%2,%3}, {%4,%5,%6,%7}, {%8,%9}, {%0,%1,%2,%3};" \
                 : "+f"((d)[0]), "+f"((d)[1]), "+f"((d)[2]), "+f"((d)[3]) \
                 : "r"((a)[0]), "r"((a)[1]), "r"((a)[2]), "r"((a)[3]), \
                   "r"(b0_), "r"(b1_))

__device__ __forceinline__ uint32_t pack_h2(__half a, __half b) {
    __half2 t = __halves2half2(a, b);
    return *reinterpret_cast<uint32_t*>(&t);
}

// -------------------------------------------------------------------------
// Kernel 1: gather tokens + fp16(A), PLUS W->fp16 convert in extra blocks.
// blocks [0, 8192): gather 4 rows each; blocks [8192, 8704): wconv.
// -------------------------------------------------------------------------
#define GATHER_BLKS (Mpad / 4)     // 8192
#define WCONV_BLKS  512

__global__ void gather_wconv_kernel(const float* __restrict__ x,
                                    const int*   __restrict__ lengths,
                                    const float* __restrict__ W,
                                    float* __restrict__ tok,
                                    float* __restrict__ out_len)
{
    const int i = threadIdx.x;

    if (blockIdx.x >= GATHER_BLKS) {      // ---- wconv part ----
        const int wi = (blockIdx.x - GATHER_BLKS) * 128 + i;   // float4 idx
        const float4 v = reinterpret_cast<const float4*>(W)[wi];
        uint2 uh;
        uh.x = pack_h2(__float2half(v.x), __float2half(v.y));
        uh.y = pack_h2(__float2half(v.z), __float2half(v.w));
        reinterpret_cast<uint2*>(g_Wh)[wi] = uh;
        return;
    }

    #pragma unroll
    for (int rr = 0; rr < 4; rr++) {
        const int row = blockIdx.x * 4 + rr;
        float4 v = make_float4(0.f, 0.f, 0.f, 0.f);
        if (row < Mrows) {
            const int b = row / Tq;
            const int t = row - b * Tq;
            const int ntok = (lengths[b] - Pq) / STRIDEq + 1;
            if (t < ntok) {
                const int p  = i >> 4;
                const int d4 = i & 15;
                v = reinterpret_cast<const float4*>(
                        x + ((size_t)b * Sq + (size_t)t * STRIDEq + p) * Dq)[d4];
            }
            reinterpret_cast<float4*>(tok + (size_t)row * Kdim)[i] = v;
        }
        uint2 uh;
        uh.x = pack_h2(__float2half(v.x), __float2half(v.y));
        uh.y = pack_h2(__float2half(v.z), __float2half(v.w));
        reinterpret_cast<uint2*>(g_Ah)[(size_t)row * 128 + i] = uh;
    }
    if (blockIdx.x == 0 && i < Bq)
        out_len[i] = (float)((lengths[i] - Pq) / STRIDEq + 1);
}

// -------------------------------------------------------------------------
// Kernel 2: plain fp16 GEMM — exact R11 winner config.
// mma.sync.m16n8k16, BK=32, 4-stage cp.async ring (3 ahead, wait_group 2),
// CTA 128x128, 128 threads = 4 warps (warp 64x64), occ 2, 1 barrier/stage.
// -------------------------------------------------------------------------
#define BKq       32
#define A_STRIDE  80
#define W_STRIDE  272
#define A_BUF     (128 * A_STRIDE)          // 10240
#define W_BUF     (BKq * W_STRIDE)          // 8704
#define STAGE_B   (A_BUF + W_BUF)           // 18944
#define NSTAGE    4
#define GEMM_SMEM (NSTAGE * STAGE_B)        // 75776 (x2 CTAs = 151.5KB/SM)

__global__ __launch_bounds__(128, 2)
void gemm_mma_kernel(const float* __restrict__ bias,
                     float* __restrict__ hidden)
{
    extern __shared__ char sm[];
    const uint32_t sbase = smem_u32(sm);

    const int tid  = threadIdx.x;
    const int n0   = blockIdx.x * 128;
    const int m0   = blockIdx.y * 128;
    const int w    = tid >> 5;
    const int lane = tid & 31;
    const int wm   = (w >> 1) * 64;
    const int wn   = (w & 1) * 64;

    float acc[4][8][4];
    #pragma unroll
    for (int a = 0; a < 4; a++)
        #pragma unroll
        for (int b = 0; b < 8; b++)
            #pragma unroll
            for (int c = 0; c < 4; c++) acc[a][b][c] = 0.f;

    auto load_stage = [&](int buf, int k0) {
        const uint32_t st = sbase + buf * STAGE_B;
        #pragma unroll
        for (int j = 0; j < 4; j++) {                 // A: 512 16B chunks
            const int i = j * 128 + tid;
            const int row = i >> 2, c = i & 3;
            CP_ASYNC16(st + row * A_STRIDE + c * 16,
                       g_Ah + (size_t)(m0 + row) * Kdim + k0 + c * 8);
        }
        #pragma unroll
        for (int j = 0; j < 4; j++) {                 // W: 512 16B chunks
            const int i = j * 128 + tid;
            const int kr = i >> 4, ch = i & 15;
            CP_ASYNC16(st + A_BUF + kr * W_STRIDE + ch * 16,
                       g_Wh + (size_t)(k0 + kr) * Hq + n0 + ch * 8);
        }
        CP_COMMIT();
    };

    // prologue: three stages in flight
    load_stage(0, 0);
    load_stage(1, BKq);
    load_stage(2, 2 * BKq);

    #pragma unroll 1
    for (int s = 0; s < 16; s++) {
        if (s >= 13) { CP_WAIT0(); } else { CP_WAIT2(); }   // stage s resident
        __syncthreads();          // all warps done with buf (s+3)%4 (read at s-1)
        if (s + 3 < 16) load_stage((s + 3) % NSTAGE, (s + 3) * BKq);

        const uint32_t st   = sbase + (s % NSTAGE) * STAGE_B;
        const uint32_t Ah_b = st;
        const uint32_t Wh_b = st + A_BUF;

        #pragma unroll
        for (int kk = 0; kk < 2; kk++) {
            const int k16 = kk * 16;
            uint32_t aX[4][4], bH[4][4];

            const int arow  = lane & 15;
            const int acolB = (k16 + ((lane >> 4) << 3)) * 2;
            const int brow  = k16 + (lane & 15);
            const int bhalf = (lane >> 4) << 3;

            #pragma unroll
            for (int im = 0; im < 4; im++)
                LDSM4(aX[im], Ah_b + (wm + im * 16 + arow) * A_STRIDE + acolB);
            #pragma unroll
            for (int in = 0; in < 4; in++)
                LDSM4T(bH[in], Wh_b + brow * W_STRIDE + (wn + in * 16 + bhalf) * 2);

            #pragma unroll
            for (int im = 0; im < 4; im++)
                #pragma unroll
                for (int in = 0; in < 4; in++) {
                    MMA16816(acc[im][2 * in],     aX[im], bH[in][0], bH[in][1]);
                    MMA16816(acc[im][2 * in + 1], aX[im], bH[in][2], bH[in][3]);
                }
        }
    }

    // ---- epilogue: + bias, guarded stores ----
    #pragma unroll
    for (int im = 0; im < 4; im++) {
        const int gm = m0 + wm + im * 16 + (lane >> 2);
        #pragma unroll
        for (int j = 0; j < 8; j++) {
            const int gn = n0 + wn + j * 8 + 2 * (lane & 3);
            const float b0 = __ldg(bias + gn), b1 = __ldg(bias + gn + 1);
            if (gm < Mrows) {
                float2 v = make_float2(acc[im][j][0] + b0, acc[im][j][1] + b1);
                *reinterpret_cast<float2*>(hidden + (size_t)gm * Hq + gn) = v;
            }
            if (gm + 8 < Mrows) {
                float2 v = make_float2(acc[im][j][2] + b0, acc[im][j][3] + b1);
                *reinterpret_cast<float2*>(hidden + (size_t)(gm + 8) * Hq + gn) = v;
            }
        }
    }
}

// -------------------------------------------------------------------------
// Kernel 3: in-place RMSNorm. 256-thread blocks, 2 rows per block
// (measured-best config).
// -------------------------------------------------------------------------
__global__ __launch_bounds__(256)
void rmsnorm_kernel(float* __restrict__ h,
                    const float* __restrict__ scale)
{
    const int rloc = threadIdx.x >> 7;
    const int row  = blockIdx.x * 2 + rloc;
    const int i    = threadIdx.x & 127;
    const int wrp  = threadIdx.x >> 5;

    float4* hp = reinterpret_cast<float4*>(h + (size_t)row * Hq);
    float4 v = hp[i];
    float ss = v.x * v.x + v.y * v.y + v.z * v.z + v.w * v.w;
    #pragma unroll
    for (int o = 16; o > 0; o >>= 1)
        ss += __shfl_down_sync(0xffffffffu, ss, o);

    __shared__ float red[8];
    if ((threadIdx.x & 31) == 0) red[wrp] = ss;
    __syncthreads();
    const int rb = rloc * 4;
    const float tot = red[rb] + red[rb + 1] + red[rb + 2] + red[rb + 3];
    const float inv = rsqrtf(tot * (1.0f / 512.0f) + 1e-6f);

    const float4 s = reinterpret_cast<const float4*>(scale)[i];
    v.x *= inv * s.x;  v.y *= inv * s.y;
    v.z *= inv * s.z;  v.w *= inv * s.w;
    hp[i] = v;
}

// -------------------------------------------------------------------------
// launch. output: [hidden M*512][token_lengths 32][tokens M*512]
// -------------------------------------------------------------------------
extern "C" void kernel_launch(void* const* d_in, const int* in_sizes, int n_in,
                              void* d_out, int out_size)
{
    const float* x       = (const float*)d_in[0];
    const int*   lengths = (const int*)  d_in[1];
    const float* W       = (const float*)d_in[2];
    const float* bias    = (const float*)d_in[3];
    const float* scale   = (const float*)d_in[4];

    float* out        = (float*)d_out;
    float* out_hidden = out;
    float* out_len    = out + (size_t)Mrows * Hq;
    float* out_tokens = out + (size_t)Mrows * Hq + Bq;

    cudaFuncSetAttribute(gemm_mma_kernel,
                         cudaFuncAttributeMaxDynamicSharedMemorySize, GEMM_SMEM);

    gather_wconv_kernel<<<GATHER_BLKS + WCONV_BLKS, 128>>>(
        x, lengths, W, out_tokens, out_len);
    gemm_mma_kernel<<<dim3(4, 256), 128, GEMM_SMEM>>>(bias, out_hidden);
    rmsnorm_kernel<<<Mrows / 2, 256>>>(out_hidden, scale);
}

// round 15
// speedup vs baseline: 1.3810x; 1.1186x over previous
#include <cuda_runtime.h>
#include <cuda_fp16.h>
#include <cstdint>

// ---------------- problem constants ----------------
#define Bq      32
#define Sq      4096
#define Dq      64
#define Pq      8
#define STRIDEq 4
#define Hq      512
#define Tq      1023
#define Mrows   (Bq * Tq)     // 32736
#define Mpad    32768
#define Kdim    512

// ---------------- device-global scratch (allocation-free rule) ----------
__device__ __align__(256) __half g_Ah[(size_t)Mpad * Kdim];  // fp16(A)
__device__ __align__(256) __half g_Wh[Kdim * Hq];            // fp16(W)

// ---------------- PTX helpers ----------------
__device__ __forceinline__ uint32_t smem_u32(const void* p) {
    uint32_t a;
    asm("{ .reg .u64 t; cvta.to.shared.u64 t, %1; cvt.u32.u64 %0, t; }" : "=r"(a) : "l"(p));
    return a;
}

#define CP_ASYNC16(dst, src) \
    asm volatile("cp.async.cg.shared.global [%0], [%1], 16;" \
                 :: "r"((uint32_t)(dst)), "l"(__cvta_generic_to_global(src)) : "memory")
#define CP_COMMIT()  asm volatile("cp.async.commit_group;" ::: "memory")
#define CP_WAIT2()   asm volatile("cp.async.wait_group 2;" ::: "memory")
#define CP_WAIT0()   asm volatile("cp.async.wait_group 0;" ::: "memory")

#define LDSM4(r, addr) \
    asm volatile("ldmatrix.sync.aligned.m8n8.x4.shared.b16 {%0,%1,%2,%3}, [%4];" \
                 : "=r"((r)[0]), "=r"((r)[1]), "=r"((r)[2]), "=r"((r)[3]) : "r"(addr))
#define LDSM4T(r, addr) \
    asm volatile("ldmatrix.sync.aligned.m8n8.x4.trans.shared.b16 {%0,%1,%2,%3}, [%4];" \
                 : "=r"((r)[0]), "=r"((r)[1]), "=r"((r)[2]), "=r"((r)[3]) : "r"(addr))

#define MMA16816(d, a, b0_, b1_) \
    asm volatile("mma.sync.aligned.m16n8k16.row.col.f32.f16.f16.f32 " \
                 "{%0,%1,%2,%3}, {%4,%5,%6,%7}, {%8,%9}, {%0,%1,%2,%3};" \
                 : "+f"((d)[0]), "+f"((d)[1]), "+f"((d)[2]), "+f"((d)[3]) \
                 : "r"((a)[0]), "r"((a)[1]), "r"((a)[2]), "r"((a)[3]), \
                   "r"(b0_), "r"(b1_))

__device__ __forceinline__ uint32_t pack_h2(__half a, __half b) {
    __half2 t = __halves2half2(a, b);
    return *reinterpret_cast<uint32_t*>(&t);
}

// -------------------------------------------------------------------------
// Kernel 1: gather tokens + fp16(A), PLUS W->fp16 convert in extra blocks.
// blocks [0, 8192): gather 4 rows each; blocks [8192, 8704): wconv.
// -------------------------------------------------------------------------
#define GATHER_BLKS (Mpad / 4)     // 8192
#define WCONV_BLKS  512

__global__ void gather_wconv_kernel(const float* __restrict__ x,
                                    const int*   __restrict__ lengths,
                                    const float* __restrict__ W,
                                    float* __restrict__ tok,
                                    float* __restrict__ out_len)
{
    const int i = threadIdx.x;

    if (blockIdx.x >= GATHER_BLKS) {      // ---- wconv part ----
        const int wi = (blockIdx.x - GATHER_BLKS) * 128 + i;   // float4 idx
        const float4 v = reinterpret_cast<const float4*>(W)[wi];
        uint2 uh;
        uh.x = pack_h2(__float2half(v.x), __float2half(v.y));
        uh.y = pack_h2(__float2half(v.z), __float2half(v.w));
        reinterpret_cast<uint2*>(g_Wh)[wi] = uh;
        return;
    }

    #pragma unroll
    for (int rr = 0; rr < 4; rr++) {
        const int row = blockIdx.x * 4 + rr;
        float4 v = make_float4(0.f, 0.f, 0.f, 0.f);
        if (row < Mrows) {
            const int b = row / Tq;
            const int t = row - b * Tq;
            const int ntok = (lengths[b] - Pq) / STRIDEq + 1;
            if (t < ntok) {
                const int p  = i >> 4;
                const int d4 = i & 15;
                v = reinterpret_cast<const float4*>(
                        x + ((size_t)b * Sq + (size_t)t * STRIDEq + p) * Dq)[d4];
            }
            reinterpret_cast<float4*>(tok + (size_t)row * Kdim)[i] = v;
        }
        uint2 uh;
        uh.x = pack_h2(__float2half(v.x), __float2half(v.y));
        uh.y = pack_h2(__float2half(v.z), __float2half(v.w));
        reinterpret_cast<uint2*>(g_Ah)[(size_t)row * 128 + i] = uh;
    }
    if (blockIdx.x == 0 && i < Bq)
        out_len[i] = (float)((lengths[i] - Pq) / STRIDEq + 1);
}

// -------------------------------------------------------------------------
// Kernel 2: plain fp16 GEMM (R11 winner config) + invalid-tile early exit.
// A tile whose rows all satisfy t >= n_tok[b] has A == 0, so h = bias:
// write bias rows directly and skip all loads/MMA. A tile crossing a batch
// boundary always contains t=0 (valid), so only single-batch tiles skip.
// mma.sync.m16n8k16, BK=32, 4-stage ring (3 ahead), 4 warps 64x64, occ 2.
// -------------------------------------------------------------------------
#define BKq       32
#define A_STRIDE  80
#define W_STRIDE  272
#define A_BUF     (128 * A_STRIDE)          // 10240
#define W_BUF     (BKq * W_STRIDE)          // 8704
#define STAGE_B   (A_BUF + W_BUF)           // 18944
#define NSTAGE    4
#define GEMM_SMEM (NSTAGE * STAGE_B)        // 75776 (x2 CTAs = 151.5KB/SM)

__global__ __launch_bounds__(128, 2)
void gemm_mma_kernel(const int*   __restrict__ lengths,
                     const float* __restrict__ bias,
                     float* __restrict__ hidden)
{
    extern __shared__ char sm[];
    const uint32_t sbase = smem_u32(sm);

    const int tid  = threadIdx.x;
    const int n0   = blockIdx.x * 128;
    const int m0   = blockIdx.y * 128;

    // ---- invalid-stripe early exit ----
    {
        const int b0   = m0 / Tq;
        const int last = (m0 + 127 < Mrows - 1) ? (m0 + 127) : (Mrows - 1);
        const int b1   = last / Tq;
        if (b0 == b1) {
            const int ntok = (lengths[b0] - Pq) / STRIDEq + 1;
            if (m0 - b0 * Tq >= ntok) {
                // all 128 rows invalid: h = bias
                const int ch = (tid & 31) * 4;              // col chunk in tile
                const float4 bv = *reinterpret_cast<const float4*>(bias + n0 + ch);
                #pragma unroll 4
                for (int it = 0; it < 32; it++) {
                    const int gm = m0 + it * 4 + (tid >> 5);
                    if (gm < Mrows)
                        *reinterpret_cast<float4*>(
                            hidden + (size_t)gm * Hq + n0 + ch) = bv;
                }
                return;
            }
        }
    }

    const int w    = tid >> 5;
    const int lane = tid & 31;
    const int wm   = (w >> 1) * 64;
    const int wn   = (w & 1) * 64;

    float acc[4][8][4];
    #pragma unroll
    for (int a = 0; a < 4; a++)
        #pragma unroll
        for (int b = 0; b < 8; b++)
            #pragma unroll
            for (int c = 0; c < 4; c++) acc[a][b][c] = 0.f;

    auto load_stage = [&](int buf, int k0) {
        const uint32_t st = sbase + buf * STAGE_B;
        #pragma unroll
        for (int j = 0; j < 4; j++) {                 // A: 512 16B chunks
            const int i = j * 128 + tid;
            const int row = i >> 2, c = i & 3;
            CP_ASYNC16(st + row * A_STRIDE + c * 16,
                       g_Ah + (size_t)(m0 + row) * Kdim + k0 + c * 8);
        }
        #pragma unroll
        for (int j = 0; j < 4; j++) {                 // W: 512 16B chunks
            const int i = j * 128 + tid;
            const int kr = i >> 4, ch = i & 15;
            CP_ASYNC16(st + A_BUF + kr * W_STRIDE + ch * 16,
                       g_Wh + (size_t)(k0 + kr) * Hq + n0 + ch * 8);
        }
        CP_COMMIT();
    };

    // prologue: three stages in flight
    load_stage(0, 0);
    load_stage(1, BKq);
    load_stage(2, 2 * BKq);

    #pragma unroll 1
    for (int s = 0; s < 16; s++) {
        if (s >= 13) { CP_WAIT0(); } else { CP_WAIT2(); }   // stage s resident
        __syncthreads();          // all warps done with buf (s+3)%4 (read at s-1)
        if (s + 3 < 16) load_stage((s + 3) % NSTAGE, (s + 3) * BKq);

        const uint32_t st   = sbase + (s % NSTAGE) * STAGE_B;
        const uint32_t Ah_b = st;
        const uint32_t Wh_b = st + A_BUF;

        #pragma unroll
        for (int kk = 0; kk < 2; kk++) {
            const int k16 = kk * 16;
            uint32_t aX[4][4], bH[4][4];

            const int arow  = lane & 15;
            const int acolB = (k16 + ((lane >> 4) << 3)) * 2;
            const int brow  = k16 + (lane & 15);
            const int bhalf = (lane >> 4) << 3;

            #pragma unroll
            for (int im = 0; im < 4; im++)
                LDSM4(aX[im], Ah_b + (wm + im * 16 + arow) * A_STRIDE + acolB);
            #pragma unroll
            for (int in = 0; in < 4; in++)
                LDSM4T(bH[in], Wh_b + brow * W_STRIDE + (wn + in * 16 + bhalf) * 2);

            #pragma unroll
            for (int im = 0; im < 4; im++)
                #pragma unroll
                for (int in = 0; in < 4; in++) {
                    MMA16816(acc[im][2 * in],     aX[im], bH[in][0], bH[in][1]);
                    MMA16816(acc[im][2 * in + 1], aX[im], bH[in][2], bH[in][3]);
                }
        }
    }

    // ---- epilogue: + bias, guarded stores ----
    #pragma unroll
    for (int im = 0; im < 4; im++) {
        const int gm = m0 + wm + im * 16 + (lane >> 2);
        #pragma unroll
        for (int j = 0; j < 8; j++) {
            const int gn = n0 + wn + j * 8 + 2 * (lane & 3);
            const float b0 = __ldg(bias + gn), b1 = __ldg(bias + gn + 1);
            if (gm < Mrows) {
                float2 v = make_float2(acc[im][j][0] + b0, acc[im][j][1] + b1);
                *reinterpret_cast<float2*>(hidden + (size_t)gm * Hq + gn) = v;
            }
            if (gm + 8 < Mrows) {
                float2 v = make_float2(acc[im][j][2] + b0, acc[im][j][3] + b1);
                *reinterpret_cast<float2*>(hidden + (size_t)(gm + 8) * Hq + gn) = v;
            }
        }
    }
}

// -------------------------------------------------------------------------
// Kernel 3: in-place RMSNorm. 256-thread blocks, 2 rows per block
// (measured-best config).
// -------------------------------------------------------------------------
__global__ __launch_bounds__(256)
void rmsnorm_kernel(float* __restrict__ h,
                    const float* __restrict__ scale)
{
    const int rloc = threadIdx.x >> 7;
    const int row  = blockIdx.x * 2 + rloc;
    const int i    = threadIdx.x & 127;
    const int wrp  = threadIdx.x >> 5;

    float4* hp = reinterpret_cast<float4*>(h + (size_t)row * Hq);
    float4 v = hp[i];
    float ss = v.x * v.x + v.y * v.y + v.z * v.z + v.w * v.w;
    #pragma unroll
    for (int o = 16; o > 0; o >>= 1)
        ss += __shfl_down_sync(0xffffffffu, ss, o);

    __shared__ float red[8];
    if ((threadIdx.x & 31) == 0) red[wrp] = ss;
    __syncthreads();
    const int rb = rloc * 4;
    const float tot = red[rb] + red[rb + 1] + red[rb + 2] + red[rb + 3];
    const float inv = rsqrtf(tot * (1.0f / 512.0f) + 1e-6f);

    const float4 s = reinterpret_cast<const float4*>(scale)[i];
    v.x *= inv * s.x;  v.y *= inv * s.y;
    v.z *= inv * s.z;  v.w *= inv * s.w;
    hp[i] = v;
}

// -------------------------------------------------------------------------
// launch. output: [hidden M*512][token_lengths 32][tokens M*512]
// -------------------------------------------------------------------------
extern "C" void kernel_launch(void* const* d_in, const int* in_sizes, int n_in,
                              void* d_out, int out_size)
{
    const float* x       = (const float*)d_in[0];
    const int*   lengths = (const int*)  d_in[1];
    const float* W       = (const float*)d_in[2];
    const float* bias    = (const float*)d_in[3];
    const float* scale   = (const float*)d_in[4];

    float* out        = (float*)d_out;
    float* out_hidden = out;
    float* out_len    = out + (size_t)Mrows * Hq;
    float* out_tokens = out + (size_t)Mrows * Hq + Bq;

    cudaFuncSetAttribute(gemm_mma_kernel,
                         cudaFuncAttributeMaxDynamicSharedMemorySize, GEMM_SMEM);

    gather_wconv_kernel<<<GATHER_BLKS + WCONV_BLKS, 128>>>(
        x, lengths, W, out_tokens, out_len);
    gemm_mma_kernel<<<dim3(4, 256), 128, GEMM_SMEM>>>(lengths, bias, out_hidden);
    rmsnorm_kernel<<<Mrows / 2, 256>>>(out_hidden, scale);
}

// round 16
// speedup vs baseline: 1.4427x; 1.0447x over previous
#include <cuda_runtime.h>
#include <cuda_fp16.h>
#include <cstdint>

// ---------------- problem constants ----------------
#define Bq      32
#define Sq      4096
#define Dq      64
#define Pq      8
#define STRIDEq 4
#define Hq      512
#define Tq      1023
#define Mrows   (Bq * Tq)     // 32736
#define Mpad    32768
#define Kdim    512

// ---------------- device-global scratch (allocation-free rule) ----------
__device__ __align__(256) __half g_Ah[(size_t)Mpad * Kdim];  // fp16(A)
__device__ __align__(256) __half g_Wh[Kdim * Hq];            // fp16(W)

// ---------------- PTX helpers ----------------
__device__ __forceinline__ uint32_t smem_u32(const void* p) {
    uint32_t a;
    asm("{ .reg .u64 t; cvta.to.shared.u64 t, %1; cvt.u32.u64 %0, t; }" : "=r"(a) : "l"(p));
    return a;
}

#define CP_ASYNC16(dst, src) \
    asm volatile("cp.async.cg.shared.global [%0], [%1], 16;" \
                 :: "r"((uint32_t)(dst)), "l"(__cvta_generic_to_global(src)) : "memory")
#define CP_COMMIT()  asm volatile("cp.async.commit_group;" ::: "memory")
#define CP_WAIT2()   asm volatile("cp.async.wait_group 2;" ::: "memory")
#define CP_WAIT0()   asm volatile("cp.async.wait_group 0;" ::: "memory")

#define LDSM4(r, addr) \
    asm volatile("ldmatrix.sync.aligned.m8n8.x4.shared.b16 {%0,%1,%2,%3}, [%4];" \
                 : "=r"((r)[0]), "=r"((r)[1]), "=r"((r)[2]), "=r"((r)[3]) : "r"(addr))
#define LDSM4T(r, addr) \
    asm volatile("ldmatrix.sync.aligned.m8n8.x4.trans.shared.b16 {%0,%1,%2,%3}, [%4];" \
                 : "=r"((r)[0]), "=r"((r)[1]), "=r"((r)[2]), "=r"((r)[3]) : "r"(addr))

#define MMA16816(d, a, b0_, b1_) \
    asm volatile("mma.sync.aligned.m16n8k16.row.col.f32.f16.f16.f32 " \
                 "{%0,%1,%2,%3}, {%4,%5,%6,%7}, {%8,%9}, {%0,%1,%2,%3};" \
                 : "+f"((d)[0]), "+f"((d)[1]), "+f"((d)[2]), "+f"((d)[3]) \
                 : "r"((a)[0]), "r"((a)[1]), "r"((a)[2]), "r"((a)[3]), \
                   "r"(b0_), "r"(b1_))

__device__ __forceinline__ uint32_t pack_h2(__half a, __half b) {
    __half2 t = __halves2half2(a, b);
    return *reinterpret_cast<uint32_t*>(&t);
}

// Stripe-skip predicate (shared by gather and GEMM): the 128-row stripe at
// m0s lies in one batch and starts at t >= n_tok -> A rows all zero.
__device__ __forceinline__ bool stripe_invalid(int m0s, const int* lengths) {
    const int b0   = m0s / Tq;
    const int last = (m0s + 127 < Mrows - 1) ? (m0s + 127) : (Mrows - 1);
    if (b0 != last / Tq) return false;
    const int ntok = (lengths[b0] - Pq) / STRIDEq + 1;
    return (m0s - b0 * Tq) >= ntok;
}

// -------------------------------------------------------------------------
// Kernel 1: gather tokens + fp16(A), PLUS W->fp16 convert in extra blocks.
// blocks [0, 8192): gather 4 rows each; blocks [8192, 8704): wconv.
// g_Ah writes are skipped for rows in fully-invalid stripes (never read).
// -------------------------------------------------------------------------
#define GATHER_BLKS (Mpad / 4)     // 8192
#define WCONV_BLKS  512

__global__ void gather_wconv_kernel(const float* __restrict__ x,
                                    const int*   __restrict__ lengths,
                                    const float* __restrict__ W,
                                    float* __restrict__ tok,
                                    float* __restrict__ out_len)
{
    const int i = threadIdx.x;

    if (blockIdx.x >= GATHER_BLKS) {      // ---- wconv part ----
        const int wi = (blockIdx.x - GATHER_BLKS) * 128 + i;   // float4 idx
        const float4 v = reinterpret_cast<const float4*>(W)[wi];
        uint2 uh;
        uh.x = pack_h2(__float2half(v.x), __float2half(v.y));
        uh.y = pack_h2(__float2half(v.z), __float2half(v.w));
        reinterpret_cast<uint2*>(g_Wh)[wi] = uh;
        return;
    }

    // all 4 rows of this block live in the same 128-row stripe
    const bool skipAh = stripe_invalid((blockIdx.x * 4) & ~127, lengths);

    #pragma unroll
    for (int rr = 0; rr < 4; rr++) {
        const int row = blockIdx.x * 4 + rr;
        float4 v = make_float4(0.f, 0.f, 0.f, 0.f);
        if (row < Mrows) {
            const int b = row / Tq;
            const int t = row - b * Tq;
            const int ntok = (lengths[b] - Pq) / STRIDEq + 1;
            if (t < ntok) {
                const int p  = i >> 4;
                const int d4 = i & 15;
                v = reinterpret_cast<const float4*>(
                        x + ((size_t)b * Sq + (size_t)t * STRIDEq + p) * Dq)[d4];
            }
            reinterpret_cast<float4*>(tok + (size_t)row * Kdim)[i] = v;
        }
        if (!skipAh) {
            uint2 uh;
            uh.x = pack_h2(__float2half(v.x), __float2half(v.y));
            uh.y = pack_h2(__float2half(v.z), __float2half(v.w));
            reinterpret_cast<uint2*>(g_Ah)[(size_t)row * 128 + i] = uh;
        }
    }
    if (blockIdx.x == 0 && i < Bq)
        out_len[i] = (float)((lengths[i] - Pq) / STRIDEq + 1);
}

// -------------------------------------------------------------------------
// Kernel 2: plain fp16 GEMM (R11 winner config) + invalid-stripe early exit.
// Skipped stripes write NOTHING (rmsnorm produces those rows from bias).
// mma.sync.m16n8k16, BK=32, 4-stage ring (3 ahead), 4 warps 64x64, occ 2.
// -------------------------------------------------------------------------
#define BKq       32
#define A_STRIDE  80
#define W_STRIDE  272
#define A_BUF     (128 * A_STRIDE)          // 10240
#define W_BUF     (BKq * W_STRIDE)          // 8704
#define STAGE_B   (A_BUF + W_BUF)           // 18944
#define NSTAGE    4
#define GEMM_SMEM (NSTAGE * STAGE_B)        // 75776 (x2 CTAs = 151.5KB/SM)

__global__ __launch_bounds__(128, 2)
void gemm_mma_kernel(const int*   __restrict__ lengths,
                     const float* __restrict__ bias,
                     float* __restrict__ hidden)
{
    extern __shared__ char sm[];
    const uint32_t sbase = smem_u32(sm);

    const int tid  = threadIdx.x;
    const int n0   = blockIdx.x * 128;
    const int m0   = blockIdx.y * 128;

    if (stripe_invalid(m0, lengths)) return;   // rows produced by rmsnorm

    const int w    = tid >> 5;
    const int lane = tid & 31;
    const int wm   = (w >> 1) * 64;
    const int wn   = (w & 1) * 64;

    float acc[4][8][4];
    #pragma unroll
    for (int a = 0; a < 4; a++)
        #pragma unroll
        for (int b = 0; b < 8; b++)
            #pragma unroll
            for (int c = 0; c < 4; c++) acc[a][b][c] = 0.f;

    auto load_stage = [&](int buf, int k0) {
        const uint32_t st = sbase + buf * STAGE_B;
        #pragma unroll
        for (int j = 0; j < 4; j++) {                 // A: 512 16B chunks
            const int i = j * 128 + tid;
            const int row = i >> 2, c = i & 3;
            CP_ASYNC16(st + row * A_STRIDE + c * 16,
                       g_Ah + (size_t)(m0 + row) * Kdim + k0 + c * 8);
        }
        #pragma unroll
        for (int j = 0; j < 4; j++) {                 // W: 512 16B chunks
            const int i = j * 128 + tid;
            const int kr = i >> 4, ch = i & 15;
            CP_ASYNC16(st + A_BUF + kr * W_STRIDE + ch * 16,
                       g_Wh + (size_t)(k0 + kr) * Hq + n0 + ch * 8);
        }
        CP_COMMIT();
    };

    // prologue: three stages in flight
    load_stage(0, 0);
    load_stage(1, BKq);
    load_stage(2, 2 * BKq);

    #pragma unroll 1
    for (int s = 0; s < 16; s++) {
        if (s >= 13) { CP_WAIT0(); } else { CP_WAIT2(); }   // stage s resident
        __syncthreads();          // all warps done with buf (s+3)%4 (read at s-1)
        if (s + 3 < 16) load_stage((s + 3) % NSTAGE, (s + 3) * BKq);

        const uint32_t st   = sbase + (s % NSTAGE) * STAGE_B;
        const uint32_t Ah_b = st;
        const uint32_t Wh_b = st + A_BUF;

        #pragma unroll
        for (int kk = 0; kk < 2; kk++) {
            const int k16 = kk * 16;
            uint32_t aX[4][4], bH[4][4];

            const int arow  = lane & 15;
            const int acolB = (k16 + ((lane >> 4) << 3)) * 2;
            const int brow  = k16 + (lane & 15);
            const int bhalf = (lane >> 4) << 3;

            #pragma unroll
            for (int im = 0; im < 4; im++)
                LDSM4(aX[im], Ah_b + (wm + im * 16 + arow) * A_STRIDE + acolB);
            #pragma unroll
            for (int in = 0; in < 4; in++)
                LDSM4T(bH[in], Wh_b + brow * W_STRIDE + (wn + in * 16 + bhalf) * 2);

            #pragma unroll
            for (int im = 0; im < 4; im++)
                #pragma unroll
                for (int in = 0; in < 4; in++) {
                    MMA16816(acc[im][2 * in],     aX[im], bH[in][0], bH[in][1]);
                    MMA16816(acc[im][2 * in + 1], aX[im], bH[in][2], bH[in][3]);
                }
        }
    }

    // ---- epilogue: + bias, guarded stores ----
    #pragma unroll
    for (int im = 0; im < 4; im++) {
        const int gm = m0 + wm + im * 16 + (lane >> 2);
        #pragma unroll
        for (int j = 0; j < 8; j++) {
            const int gn = n0 + wn + j * 8 + 2 * (lane & 3);
            const float b0 = __ldg(bias + gn), b1 = __ldg(bias + gn + 1);
            if (gm < Mrows) {
                float2 v = make_float2(acc[im][j][0] + b0, acc[im][j][1] + b1);
                *reinterpret_cast<float2*>(hidden + (size_t)gm * Hq + gn) = v;
            }
            if (gm + 8 < Mrows) {
                float2 v = make_float2(acc[im][j][2] + b0, acc[im][j][3] + b1);
                *reinterpret_cast<float2*>(hidden + (size_t)(gm + 8) * Hq + gn) = v;
            }
        }
    }
}

// -------------------------------------------------------------------------
// Kernel 3: RMSNorm. 256-thread blocks, 2 rows per block.
// Invalid rows (t >= n_tok): source = bias (h for those rows is bias or
// never written); result = bias / rms(bias) * scale, written unconditionally.
// -------------------------------------------------------------------------
__global__ __launch_bounds__(256)
void rmsnorm_kernel(float* __restrict__ h,
                    const float* __restrict__ scale,
                    const float* __restrict__ bias,
                    const int*   __restrict__ lengths)
{
    const int rloc = threadIdx.x >> 7;
    const int row  = blockIdx.x * 2 + rloc;
    const int i    = threadIdx.x & 127;
    const int wrp  = threadIdx.x >> 5;

    const int b    = row / Tq;
    const int t    = row - b * Tq;
    const int ntok = (lengths[b] - Pq) / STRIDEq + 1;
    const bool valid = (t < ntok);

    float4* hp = reinterpret_cast<float4*>(h + (size_t)row * Hq);
    float4 v = valid ? hp[i]
                     : reinterpret_cast<const float4*>(bias)[i];

    float ss = v.x * v.x + v.y * v.y + v.z * v.z + v.w * v.w;
    #pragma unroll
    for (int o = 16; o > 0; o >>= 1)
        ss += __shfl_down_sync(0xffffffffu, ss, o);

    __shared__ float red[8];
    if ((threadIdx.x & 31) == 0) red[wrp] = ss;
    __syncthreads();
    const int rb = rloc * 4;
    const float tot = red[rb] + red[rb + 1] + red[rb + 2] + red[rb + 3];
    const float inv = rsqrtf(tot * (1.0f / 512.0f) + 1e-6f);

    const float4 s = reinterpret_cast<const float4*>(scale)[i];
    v.x *= inv * s.x;  v.y *= inv * s.y;
    v.z *= inv * s.z;  v.w *= inv * s.w;
    hp[i] = v;
}

// -------------------------------------------------------------------------
// launch. output: [hidden M*512][token_lengths 32][tokens M*512]
// -------------------------------------------------------------------------
extern "C" void kernel_launch(void* const* d_in, const int* in_sizes, int n_in,
                              void* d_out, int out_size)
{
    const float* x       = (const float*)d_in[0];
    const int*   lengths = (const int*)  d_in[1];
    const float* W       = (const float*)d_in[2];
    const float* bias    = (const float*)d_in[3];
    const float* scale   = (const float*)d_in[4];

    float* out        = (float*)d_out;
    float* out_hidden = out;
    float* out_len    = out + (size_t)Mrows * Hq;
    float* out_tokens = out + (size_t)Mrows * Hq + Bq;

    cudaFuncSetAttribute(gemm_mma_kernel,
                         cudaFuncAttributeMaxDynamicSharedMemorySize, GEMM_SMEM);

    gather_wconv_kernel<<<GATHER_BLKS + WCONV_BLKS, 128>>>(
        x, lengths, W, out_tokens, out_len);
    gemm_mma_kernel<<<dim3(4, 256), 128, GEMM_SMEM>>>(lengths, bias, out_hidden);
    rmsnorm_kernel<<<Mrows / 2, 256>>>(out_hidden, scale, bias, lengths);
}